// round 9
// baseline (speedup 1.0000x reference)
#include <cuda_runtime.h>
#include <cooperative_groups.h>
namespace cg = cooperative_groups;

#define THETA 0.5f
#define EPS   1e-5f

__device__ __forceinline__ float fast_tanh(float x) {
    float y;
    asm("tanh.approx.f32 %0, %1;" : "=f"(y) : "f"(x));
    return y;
}

__device__ __forceinline__ unsigned smem_u32(const void* p) {
    return (unsigned)__cvta_generic_to_shared(p);
}

// Cluster of 2 CTAs per (B,C) plane; CTA rank r owns rows [128r, 128r+128).
// 256 threads = 8 warps; warp w owns 64x64 patch (prow = 2r + (w>>2), pcol = w&3).
// Stats exchange: each CTA PUSHES its half-plane (sum,sumsq) into the peer's
// smem via st.async + mbarrier complete_tx (no mid-kernel cluster.sync).
// The wait is overlapped with: level-1/2 coeffs, softmax, and the first two
// phase-2 chunk loads (stat-independent). Phase 2: reverse-order L2-hot
// re-read, distance-2 software pipeline, streaming stores.
__global__ __launch_bounds__(256, 8) __cluster_dims__(2, 1, 1)
void pmfm_fused(const float* __restrict__ x,
                const float* __restrict__ lw,
                float* __restrict__ out) {
    cg::cluster_group cluster = cg::this_cluster();
    const unsigned rank = cluster.block_rank();

    const int bc   = blockIdx.x >> 1;     // plane
    const int t    = threadIdx.x;
    const int w    = t >> 5;              // warp 0..7 = local patch
    const int lane = t & 31;
    const int prow = (int)rank * 2 + (w >> 2);
    const int pcol = w & 3;

    __shared__ float2 st[8];                       // local 8 patch stats
    __shared__ float2 sh_half;                     // own half-plane total
    __shared__ alignas(8) float2 peer_half;        // peer writes here
    __shared__ alignas(8) unsigned long long mbar; // signaled by peer's push

    // Init mbarrier, then one cluster barrier so no push can beat an init.
    if (t == 0) {
        const unsigned mb = smem_u32(&mbar);
        asm volatile("mbarrier.init.shared.b64 [%0], 1;" :: "r"(mb) : "memory");
    }
    asm volatile("barrier.cluster.arrive.aligned;" ::: "memory");
    asm volatile("barrier.cluster.wait.aligned;"   ::: "memory");

    const float* plane = x + (size_t)bc * 65536;
    float* oplane      = out + (size_t)bc * 65536;
    const int colf  = pcol * 64 + (lane & 15) * 4;
    const int rbase = prow * 64 + (lane >> 4);

    const float4* pin4 = reinterpret_cast<const float4*>(plane + (size_t)rbase * 256 + colf);
    float4*       po4  = reinterpret_cast<float4*>(oplane + (size_t)rbase * 256 + colf);

    // ---- Phase 1: per-patch moments, 4-deep batches, dual accumulators ----
    float sA = 0.f, sB = 0.f, qA = 0.f, qB = 0.f;
#pragma unroll
    for (int c = 0; c < 8; ++c) {
        const float4 va = pin4[(size_t)(4 * c + 0) * 128];
        const float4 vb = pin4[(size_t)(4 * c + 1) * 128];
        const float4 vc = pin4[(size_t)(4 * c + 2) * 128];
        const float4 vd = pin4[(size_t)(4 * c + 3) * 128];
        sA += (va.x + va.y) + (va.z + va.w);
        qA += va.x * va.x + va.y * va.y + va.z * va.z + va.w * va.w;
        sB += (vb.x + vb.y) + (vb.z + vb.w);
        qB += vb.x * vb.x + vb.y * vb.y + vb.z * vb.z + vb.w * vb.w;
        sA += (vc.x + vc.y) + (vc.z + vc.w);
        qA += vc.x * vc.x + vc.y * vc.y + vc.z * vc.z + vc.w * vc.w;
        sB += (vd.x + vd.y) + (vd.z + vd.w);
        qB += vd.x * vd.x + vd.y * vd.y + vd.z * vd.z + vd.w * vd.w;
    }
    float s = sA + sB, ss = qA + qB;
#pragma unroll
    for (int o = 16; o > 0; o >>= 1) {
        s  += __shfl_xor_sync(0xffffffffu, s,  o);
        ss += __shfl_xor_sync(0xffffffffu, ss, o);
    }
    if (lane == 0) st[w] = make_float2(s, ss);
    __syncthreads();
    if (t < 8) {
        float2 v = st[t];
        float hs = v.x, hq = v.y;
#pragma unroll
        for (int o = 4; o > 0; o >>= 1) {
            hs += __shfl_xor_sync(0x000000ffu, hs, o, 8);
            hq += __shfl_xor_sync(0x000000ffu, hq, o, 8);
        }
        if (t == 0) sh_half = make_float2(hs, hq);
    }
    __syncthreads();               // st + sh_half visible CTA-locally

    // ---- Push own half total into peer's smem; post local expect_tx ----
    if (t == 0) {
        const unsigned mb = smem_u32(&mbar);
        // local: single arrival + expect 8 tx bytes from the peer's push
        asm volatile("mbarrier.arrive.expect_tx.shared.b64 _, [%0], 8;"
                     :: "r"(mb) : "memory");
        unsigned peer_data, peer_mb;
        asm volatile("mapa.shared::cluster.u32 %0, %1, %2;"
                     : "=r"(peer_data) : "r"(smem_u32(&peer_half)), "r"(rank ^ 1u));
        asm volatile("mapa.shared::cluster.u32 %0, %1, %2;"
                     : "=r"(peer_mb) : "r"(mb), "r"(rank ^ 1u));
        const float2 h = sh_half;
        unsigned long long payload;
        asm volatile("mov.b64 %0, {%1, %2};" : "=l"(payload) : "f"(h.x), "f"(h.y));
        asm volatile("st.async.shared::cluster.mbarrier::complete_tx::bytes.b64 "
                     "[%0], %1, [%2];"
                     :: "r"(peer_data), "l"(payload), "r"(peer_mb) : "memory");
    }

    // ---- Overlap window: everything not needing level-0 stats ----
    // Prime phase-2 pipeline (chunks 15, 14) — stat-independent L2 re-reads.
    float4 buf[2][2];
    buf[1][0] = __ldcs(&pin4[(size_t)(2 * 15 + 0) * 128]);
    buf[1][1] = __ldcs(&pin4[(size_t)(2 * 15 + 1) * 128]);
    buf[0][0] = __ldcs(&pin4[(size_t)(2 * 14 + 0) * 128]);
    buf[0][1] = __ldcs(&pin4[(size_t)(2 * 14 + 1) * 128]);

    const float2 f2 = st[w];                        // level 2: own patch
    float s1 = 0.f, q1 = 0.f;                       // level 1: 2x2 quadrant
    {
        const int qc = pcol & ~1;
#pragma unroll
        for (int dr = 0; dr < 2; ++dr)
#pragma unroll
            for (int dc = 0; dc < 2; ++dc) {
                const float2 v = st[dr * 4 + (qc + dc)];
                s1 += v.x; q1 += v.y;
            }
    }
    const float iN2 = 1.f / 4096.f, iN1 = 1.f / 16384.f, iN0 = 1.f / 65536.f;
    const float mu2 = f2.x * iN2; const float v2 = fmaxf(f2.y * iN2 - mu2 * mu2, 0.f);
    const float mu1 = s1  * iN1; const float v1 = fmaxf(q1  * iN1 - mu1 * mu1, 0.f);
    const float a2 = 0.5f * rsqrtf(v2 + EPS), b2 = -mu2 * a2;
    const float a1 = 0.5f * rsqrtf(v1 + EPS), b1 = -mu1 * a1;

    const float w0 = __ldg(lw + 0), w1 = __ldg(lw + 1), w2 = __ldg(lw + 2);
    const float m  = fmaxf(w0, fmaxf(w1, w2));
    const float e0 = __expf(w0 - m), e1 = __expf(w1 - m), e2 = __expf(w2 - m);
    const float cc = (1.f - THETA) * 0.5f / (e0 + e1 + e2);
    const float cf = cc * e0, cm = cc * e1, cg_ = cc * e2;
    const float basew = THETA + (1.f - THETA) * 0.5f;

    const float2 own_half = sh_half;

    // ---- Wait for peer's push (acquire), finish level-0 coeffs ----
    {
        const unsigned mb = smem_u32(&mbar);
        unsigned done;
        asm volatile(
            "{\n\t.reg .pred p;\n\t"
            "mbarrier.try_wait.parity.acquire.cta.shared::cta.b64 p, [%1], 0;\n\t"
            "selp.b32 %0, 1, 0, p;\n\t}"
            : "=r"(done) : "r"(mb) : "memory");
        if (!done) {
            asm volatile(
                "{\n\t.reg .pred P1;\n\t"
                "WAIT_LOOP_%=:\n\t"
                "mbarrier.try_wait.parity.acquire.cta.shared::cta.b64 P1, [%0], 0, 0x989680;\n\t"
                "@P1 bra.uni WAIT_DONE_%=;\n\t"
                "bra.uni WAIT_LOOP_%=;\n\t"
                "WAIT_DONE_%=:\n\t}"
                :: "r"(mb) : "memory");
        }
    }
    const float2 ph = peer_half;
    const float s0 = own_half.x + ph.x;             // level 0: whole plane
    const float q0 = own_half.y + ph.y;
    const float mu0 = s0 * iN0; const float v0 = fmaxf(q0 * iN0 - mu0 * mu0, 0.f);
    const float a0 = 0.5f * rsqrtf(v0 + EPS), b0 = -mu0 * a0;

    // ---- Phase 2: reverse L2-hot re-read, distance-2 pipeline ----
#pragma unroll
    for (int c = 15; c >= 0; --c) {
        const float4 cur0 = buf[c & 1][0];
        const float4 cur1 = buf[c & 1][1];
        if (c >= 2) {
            buf[c & 1][0] = __ldcs(&pin4[(size_t)(2 * (c - 2) + 0) * 128]);
            buf[c & 1][1] = __ldcs(&pin4[(size_t)(2 * (c - 2) + 1) * 128]);
        }
        float4 in[2] = {cur0, cur1};
#pragma unroll
        for (int j = 0; j < 2; ++j) {
            float4 res;
#define PMFM_DO(comp)                                                          \
            {                                                                  \
                const float xx = in[j].comp;                                   \
                const float tf = fast_tanh(fmaf(xx, a2, b2));                  \
                const float tm = fast_tanh(fmaf(xx, a1, b1));                  \
                const float tg = fast_tanh(fmaf(xx, a0, b0));                  \
                const float f  = fmaf(cf, tf, fmaf(cm, tm, fmaf(cg_, tg, basew))); \
                res.comp = xx * f;                                             \
            }
            PMFM_DO(x) PMFM_DO(y) PMFM_DO(z) PMFM_DO(w)
#undef PMFM_DO
            __stcs(&po4[(size_t)(2 * c + j) * 128], res);
        }
    }
    // No trailing cluster barrier needed: our exit is preceded by the peer's
    // push having landed (we waited on it), and the peer likewise waits on
    // ours before entering its ~30us phase 2.
}

extern "C" void kernel_launch(void* const* d_in, const int* in_sizes, int n_in,
                              void* d_out, int out_size) {
    const float* x;
    const float* lw;
    long nx;
    if (in_sizes[0] >= in_sizes[1]) {
        x = (const float*)d_in[0]; lw = (const float*)d_in[1]; nx = in_sizes[0];
    } else {
        x = (const float*)d_in[1]; lw = (const float*)d_in[0]; nx = in_sizes[1];
    }
    const int nplanes = (int)(nx / 65536);   // B*C = 512 planes of 256x256
    pmfm_fused<<<nplanes * 2, 256>>>(x, lw, (float*)d_out);
}

// round 10
// speedup vs baseline: 1.2000x; 1.2000x over previous
#include <cuda_runtime.h>
#include <cooperative_groups.h>
namespace cg = cooperative_groups;

#define THETA 0.5f
#define EPS   1e-5f

__device__ __forceinline__ float fast_tanh(float x) {
    float y;
    asm("tanh.approx.f32 %0, %1;" : "=f"(y) : "f"(x));
    return y;
}

// Cluster of 2 CTAs owns TWO adjacent planes A=2j, B=2j+1; CTA rank r owns
// rows [128r, 128r+128) of both. 256 threads = 8 warps; warp w = 64x64 patch.
// Stage 1: stats(A) + exchange (cluster.sync + DSMEM pull, as in the proven
// R8 pattern). Stage 2 (the point of this design): B's stats loads (DRAM
// reads) are instruction-interleaved with A's gate+store (L2 re-read + DRAM
// writes) so the chip mixes read and write traffic instead of alternating
// read-only / write-only phases. Stage 3: exchange B stats, gate+store B.
__global__ __launch_bounds__(256, 4) __cluster_dims__(2, 1, 1)
void pmfm_fused(const float* __restrict__ x,
                const float* __restrict__ lw,
                float* __restrict__ out) {
    cg::cluster_group cluster = cg::this_cluster();
    const unsigned rank = cluster.block_rank();

    const int cid  = blockIdx.x >> 1;     // cluster id -> planes 2*cid, 2*cid+1
    const int t    = threadIdx.x;
    const int w    = t >> 5;              // warp 0..7 = local patch
    const int lane = t & 31;
    const int prow = (int)rank * 2 + (w >> 2);
    const int pcol = w & 3;

    const size_t planeA = (size_t)(2 * cid) * 65536;
    const int colf  = pcol * 64 + (lane & 15) * 4;
    const int rbase = prow * 64 + (lane >> 4);      // start row (stride 2)
    const size_t off = (size_t)rbase * 256 + colf;

    const float4* pinA = reinterpret_cast<const float4*>(x + planeA + off);
    const float4* pinB = reinterpret_cast<const float4*>(x + planeA + 65536 + off);
    float4*       poA  = reinterpret_cast<float4*>(out + planeA + off);
    float4*       poB  = reinterpret_cast<float4*>(out + planeA + 65536 + off);

    __shared__ float2 st[8];        // per-patch stats (reused for A then B)
    __shared__ float2 sh_half;      // this CTA's half-plane total (A then B)

    // softmax(level_weights) — constant for both planes
    const float w0 = __ldg(lw + 0), w1 = __ldg(lw + 1), w2 = __ldg(lw + 2);
    const float mmx = fmaxf(w0, fmaxf(w1, w2));
    const float ew0 = __expf(w0 - mmx), ew1 = __expf(w1 - mmx), ew2 = __expf(w2 - mmx);
    const float cc = (1.f - THETA) * 0.5f / (ew0 + ew1 + ew2);
    const float cf = cc * ew0, cm = cc * ew1, cg_ = cc * ew2;
    const float basew = THETA + (1.f - THETA) * 0.5f;
    const float iN2 = 1.f / 4096.f, iN1 = 1.f / 16384.f, iN0 = 1.f / 65536.f;

    // ================= Stage 1: stats over plane A =================
    float sA = 0.f, sB_ = 0.f, qA = 0.f, qB_ = 0.f;
#pragma unroll
    for (int c = 0; c < 8; ++c) {
        const float4 va = pinA[(size_t)(4 * c + 0) * 128];
        const float4 vb = pinA[(size_t)(4 * c + 1) * 128];
        const float4 vc = pinA[(size_t)(4 * c + 2) * 128];
        const float4 vd = pinA[(size_t)(4 * c + 3) * 128];
        sA  += (va.x + va.y) + (va.z + va.w);
        qA  += va.x * va.x + va.y * va.y + va.z * va.z + va.w * va.w;
        sB_ += (vb.x + vb.y) + (vb.z + vb.w);
        qB_ += vb.x * vb.x + vb.y * vb.y + vb.z * vb.z + vb.w * vb.w;
        sA  += (vc.x + vc.y) + (vc.z + vc.w);
        qA  += vc.x * vc.x + vc.y * vc.y + vc.z * vc.z + vc.w * vc.w;
        sB_ += (vd.x + vd.y) + (vd.z + vd.w);
        qB_ += vd.x * vd.x + vd.y * vd.y + vd.z * vd.z + vd.w * vd.w;
    }
    float s = sA + sB_, ss = qA + qB_;
#pragma unroll
    for (int o = 16; o > 0; o >>= 1) {
        s  += __shfl_xor_sync(0xffffffffu, s,  o);
        ss += __shfl_xor_sync(0xffffffffu, ss, o);
    }
    if (lane == 0) st[w] = make_float2(s, ss);
    __syncthreads();
    if (t < 8) {
        float2 v = st[t];
        float hs = v.x, hq = v.y;
#pragma unroll
        for (int o = 4; o > 0; o >>= 1) {
            hs += __shfl_xor_sync(0x000000ffu, hs, o, 8);
            hq += __shfl_xor_sync(0x000000ffu, hq, o, 8);
        }
        if (t == 0) sh_half = make_float2(hs, hq);
    }
    cluster.sync();

    // exchange A: pull peer's half-plane total
    float phs, phq;
    {
        float2 ph = make_float2(0.f, 0.f);
        if (lane == 0)
            ph = *(const float2*)cluster.map_shared_rank((void*)&sh_half, rank ^ 1u);
        phs = __shfl_sync(0xffffffffu, ph.x, 0);
        phq = __shfl_sync(0xffffffffu, ph.y, 0);
    }
    // coefficients for A
    float a2c, b2c, a1c, b1c, a0c, b0c;
    {
        const float2 f2 = st[w];
        float s1 = 0.f, q1 = 0.f;
        const int qc = pcol & ~1;
#pragma unroll
        for (int dr = 0; dr < 2; ++dr)
#pragma unroll
            for (int dc = 0; dc < 2; ++dc) {
                const float2 v = st[dr * 4 + (qc + dc)];
                s1 += v.x; q1 += v.y;
            }
        const float s0 = sh_half.x + phs, q0 = sh_half.y + phq;
        const float mu2 = f2.x * iN2; const float v2 = fmaxf(f2.y * iN2 - mu2 * mu2, 0.f);
        const float mu1 = s1  * iN1; const float v1 = fmaxf(q1  * iN1 - mu1 * mu1, 0.f);
        const float mu0 = s0  * iN0; const float v0 = fmaxf(q0  * iN0 - mu0 * mu0, 0.f);
        a2c = 0.5f * rsqrtf(v2 + EPS); b2c = -mu2 * a2c;
        a1c = 0.5f * rsqrtf(v1 + EPS); b1c = -mu1 * a1c;
        a0c = 0.5f * rsqrtf(v0 + EPS); b0c = -mu0 * a0c;
    }

#define PMFM_GATE(res, vin, A2, B2, A1, B1, A0, B0)                            \
    {                                                                          \
        float4 _v = (vin);                                                     \
        float* _r = (float*)&(res);                                            \
        const float* _x = (const float*)&_v;                                   \
        _Pragma("unroll")                                                      \
        for (int _k = 0; _k < 4; ++_k) {                                       \
            const float xx = _x[_k];                                           \
            const float tf = fast_tanh(fmaf(xx, A2, B2));                      \
            const float tm = fast_tanh(fmaf(xx, A1, B1));                      \
            const float tg = fast_tanh(fmaf(xx, A0, B0));                      \
            _r[_k] = xx * fmaf(cf, tf, fmaf(cm, tm, fmaf(cg_, tg, basew)));    \
        }                                                                      \
    }

    // ===== Stage 2: interleave B stats-reads (DRAM) with A gate+store =====
    float sb0 = 0.f, sb1 = 0.f, qb0 = 0.f, qb1 = 0.f;
#pragma unroll
    for (int c = 0; c < 16; ++c) {
        // B reads (forward, DRAM) — issued first so they overlap A's compute
        const float4 vb0 = pinB[(size_t)(2 * c + 0) * 128];
        const float4 vb1 = pinB[(size_t)(2 * c + 1) * 128];
        // A re-reads (reverse, L2-hot)
        const float4 va0 = __ldcs(&pinA[(size_t)(2 * (15 - c) + 0) * 128]);
        const float4 va1 = __ldcs(&pinA[(size_t)(2 * (15 - c) + 1) * 128]);
        // accumulate B stats (cheap)
        sb0 += (vb0.x + vb0.y) + (vb0.z + vb0.w);
        qb0 += vb0.x * vb0.x + vb0.y * vb0.y + vb0.z * vb0.z + vb0.w * vb0.w;
        sb1 += (vb1.x + vb1.y) + (vb1.z + vb1.w);
        qb1 += vb1.x * vb1.x + vb1.y * vb1.y + vb1.z * vb1.z + vb1.w * vb1.w;
        // gate + store A
        float4 r0, r1;
        PMFM_GATE(r0, va0, a2c, b2c, a1c, b1c, a0c, b0c);
        PMFM_GATE(r1, va1, a2c, b2c, a1c, b1c, a0c, b0c);
        __stcs(&poA[(size_t)(2 * (15 - c) + 0) * 128], r0);
        __stcs(&poA[(size_t)(2 * (15 - c) + 1) * 128], r1);
    }

    // ================= Stage 3: B stats exchange + apply =================
    float bs = sb0 + sb1, bq = qb0 + qb1;
#pragma unroll
    for (int o = 16; o > 0; o >>= 1) {
        bs += __shfl_xor_sync(0xffffffffu, bs, o);
        bq += __shfl_xor_sync(0xffffffffu, bq, o);
    }
    __syncthreads();               // everyone done reading st[] for A
    if (lane == 0) st[w] = make_float2(bs, bq);
    __syncthreads();
    if (t < 8) {
        float2 v = st[t];
        float hs = v.x, hq = v.y;
#pragma unroll
        for (int o = 4; o > 0; o >>= 1) {
            hs += __shfl_xor_sync(0x000000ffu, hs, o, 8);
            hq += __shfl_xor_sync(0x000000ffu, hq, o, 8);
        }
        if (t == 0) sh_half = make_float2(hs, hq);
    }
    cluster.sync();
    {
        float2 ph = make_float2(0.f, 0.f);
        if (lane == 0)
            ph = *(const float2*)cluster.map_shared_rank((void*)&sh_half, rank ^ 1u);
        phs = __shfl_sync(0xffffffffu, ph.x, 0);
        phq = __shfl_sync(0xffffffffu, ph.y, 0);
    }
    // Early arrive: done reading peer smem; matching wait at kernel end.
    asm volatile("barrier.cluster.arrive.aligned;" ::: "memory");
    {
        const float2 f2 = st[w];
        float s1 = 0.f, q1 = 0.f;
        const int qc = pcol & ~1;
#pragma unroll
        for (int dr = 0; dr < 2; ++dr)
#pragma unroll
            for (int dc = 0; dc < 2; ++dc) {
                const float2 v = st[dr * 4 + (qc + dc)];
                s1 += v.x; q1 += v.y;
            }
        const float s0 = sh_half.x + phs, q0 = sh_half.y + phq;
        const float mu2 = f2.x * iN2; const float v2 = fmaxf(f2.y * iN2 - mu2 * mu2, 0.f);
        const float mu1 = s1  * iN1; const float v1 = fmaxf(q1  * iN1 - mu1 * mu1, 0.f);
        const float mu0 = s0  * iN0; const float v0 = fmaxf(q0  * iN0 - mu0 * mu0, 0.f);
        a2c = 0.5f * rsqrtf(v2 + EPS); b2c = -mu2 * a2c;
        a1c = 0.5f * rsqrtf(v1 + EPS); b1c = -mu1 * a1c;
        a0c = 0.5f * rsqrtf(v0 + EPS); b0c = -mu0 * a0c;
    }
    // apply B: reverse-order L2-hot re-read, double-buffered
    float4 buf[2][2];
    buf[1][0] = __ldcs(&pinB[(size_t)(2 * 15 + 0) * 128]);
    buf[1][1] = __ldcs(&pinB[(size_t)(2 * 15 + 1) * 128]);
#pragma unroll
    for (int c = 15; c >= 0; --c) {
        const float4 cur0 = buf[c & 1][0];
        const float4 cur1 = buf[c & 1][1];
        if (c > 0) {
            buf[(c - 1) & 1][0] = __ldcs(&pinB[(size_t)(2 * (c - 1) + 0) * 128]);
            buf[(c - 1) & 1][1] = __ldcs(&pinB[(size_t)(2 * (c - 1) + 1) * 128]);
        }
        float4 r0, r1;
        PMFM_GATE(r0, cur0, a2c, b2c, a1c, b1c, a0c, b0c);
        PMFM_GATE(r1, cur1, a2c, b2c, a1c, b1c, a0c, b0c);
        __stcs(&poB[(size_t)(2 * c + 0) * 128], r0);
        __stcs(&poB[(size_t)(2 * c + 1) * 128], r1);
    }
#undef PMFM_GATE

    // No CTA exits while its peer might still read sh_half.
    asm volatile("barrier.cluster.wait.aligned;" ::: "memory");
}

extern "C" void kernel_launch(void* const* d_in, const int* in_sizes, int n_in,
                              void* d_out, int out_size) {
    const float* x;
    const float* lw;
    long nx;
    if (in_sizes[0] >= in_sizes[1]) {
        x = (const float*)d_in[0]; lw = (const float*)d_in[1]; nx = in_sizes[0];
    } else {
        x = (const float*)d_in[1]; lw = (const float*)d_in[0]; nx = in_sizes[1];
    }
    const int nplanes = (int)(nx / 65536);   // B*C = 512 planes of 256x256
    pmfm_fused<<<nplanes, 256>>>(x, lw, (float*)d_out);   // 2 planes / cluster
}

// round 11
// speedup vs baseline: 1.2064x; 1.0053x over previous
#include <cuda_runtime.h>
#include <cuda_fp16.h>
#include <cooperative_groups.h>
namespace cg = cooperative_groups;

#define THETA 0.5f
#define EPS   1e-5f

__device__ __forceinline__ unsigned fast_tanh_h2(unsigned x) {
    unsigned y;
    asm("tanh.approx.f16x2 %0, %1;" : "=r"(y) : "r"(x));
    return y;
}
__device__ __forceinline__ unsigned pack_h2(float a, float b) {
    unsigned r;
    asm("cvt.rn.f16x2.f32 %0, %1, %2;" : "=r"(r) : "f"(b), "f"(a));
    return r;
}

// Cluster of 2 CTAs owns TWO adjacent planes A=2j, B=2j+1; CTA rank r owns
// rows [128r, 128r+128) of both. 256 threads = 8 warps; warp w = 64x64 patch.
// Stage 1: stats(A) + exchange (cluster.sync + DSMEM pull). Stage 2: B's
// stats loads (DRAM reads) instruction-interleaved with A's gate+store.
// Stage 3: exchange B stats, gate+store B (reverse, L2-hot).
// Gate tanh evaluated 2-at-a-time via tanh.approx.f16x2 (args + blend in f32)
// to halve MUFU pressure, which round-10 analysis showed co-limits stages 2-3.
__global__ __launch_bounds__(256, 4) __cluster_dims__(2, 1, 1)
void pmfm_fused(const float* __restrict__ x,
                const float* __restrict__ lw,
                float* __restrict__ out) {
    cg::cluster_group cluster = cg::this_cluster();
    const unsigned rank = cluster.block_rank();

    const int cid  = blockIdx.x >> 1;     // cluster id -> planes 2*cid, 2*cid+1
    const int t    = threadIdx.x;
    const int w    = t >> 5;              // warp 0..7 = local patch
    const int lane = t & 31;
    const int prow = (int)rank * 2 + (w >> 2);
    const int pcol = w & 3;

    const size_t planeA = (size_t)(2 * cid) * 65536;
    const int colf  = pcol * 64 + (lane & 15) * 4;
    const int rbase = prow * 64 + (lane >> 4);      // start row (stride 2)
    const size_t off = (size_t)rbase * 256 + colf;

    const float4* pinA = reinterpret_cast<const float4*>(x + planeA + off);
    const float4* pinB = reinterpret_cast<const float4*>(x + planeA + 65536 + off);
    float4*       poA  = reinterpret_cast<float4*>(out + planeA + off);
    float4*       poB  = reinterpret_cast<float4*>(out + planeA + 65536 + off);

    __shared__ float2 st[8];        // per-patch stats (reused for A then B)
    __shared__ float2 sh_half;      // this CTA's half-plane total (A then B)

    // softmax(level_weights) — constant for both planes
    const float w0 = __ldg(lw + 0), w1 = __ldg(lw + 1), w2 = __ldg(lw + 2);
    const float mmx = fmaxf(w0, fmaxf(w1, w2));
    const float ew0 = __expf(w0 - mmx), ew1 = __expf(w1 - mmx), ew2 = __expf(w2 - mmx);
    const float cc = (1.f - THETA) * 0.5f / (ew0 + ew1 + ew2);
    const float cf = cc * ew0, cm = cc * ew1, cg_ = cc * ew2;
    const float basew = THETA + (1.f - THETA) * 0.5f;
    const float iN2 = 1.f / 4096.f, iN1 = 1.f / 16384.f, iN0 = 1.f / 65536.f;

    // ================= Stage 1: stats over plane A =================
    float sA = 0.f, sB_ = 0.f, qA = 0.f, qB_ = 0.f;
#pragma unroll
    for (int c = 0; c < 8; ++c) {
        const float4 va = pinA[(size_t)(4 * c + 0) * 128];
        const float4 vb = pinA[(size_t)(4 * c + 1) * 128];
        const float4 vc = pinA[(size_t)(4 * c + 2) * 128];
        const float4 vd = pinA[(size_t)(4 * c + 3) * 128];
        sA  += (va.x + va.y) + (va.z + va.w);
        qA  += va.x * va.x + va.y * va.y + va.z * va.z + va.w * va.w;
        sB_ += (vb.x + vb.y) + (vb.z + vb.w);
        qB_ += vb.x * vb.x + vb.y * vb.y + vb.z * vb.z + vb.w * vb.w;
        sA  += (vc.x + vc.y) + (vc.z + vc.w);
        qA  += vc.x * vc.x + vc.y * vc.y + vc.z * vc.z + vc.w * vc.w;
        sB_ += (vd.x + vd.y) + (vd.z + vd.w);
        qB_ += vd.x * vd.x + vd.y * vd.y + vd.z * vd.z + vd.w * vd.w;
    }
    float s = sA + sB_, ss = qA + qB_;
#pragma unroll
    for (int o = 16; o > 0; o >>= 1) {
        s  += __shfl_xor_sync(0xffffffffu, s,  o);
        ss += __shfl_xor_sync(0xffffffffu, ss, o);
    }
    if (lane == 0) st[w] = make_float2(s, ss);
    __syncthreads();
    if (t < 8) {
        float2 v = st[t];
        float hs = v.x, hq = v.y;
#pragma unroll
        for (int o = 4; o > 0; o >>= 1) {
            hs += __shfl_xor_sync(0x000000ffu, hs, o, 8);
            hq += __shfl_xor_sync(0x000000ffu, hq, o, 8);
        }
        if (t == 0) sh_half = make_float2(hs, hq);
    }
    cluster.sync();

    // exchange A: pull peer's half-plane total
    float phs, phq;
    {
        float2 ph = make_float2(0.f, 0.f);
        if (lane == 0)
            ph = *(const float2*)cluster.map_shared_rank((void*)&sh_half, rank ^ 1u);
        phs = __shfl_sync(0xffffffffu, ph.x, 0);
        phq = __shfl_sync(0xffffffffu, ph.y, 0);
    }
    // coefficients for A
    float a2c, b2c, a1c, b1c, a0c, b0c;
    {
        const float2 f2 = st[w];
        float s1 = 0.f, q1 = 0.f;
        const int qc = pcol & ~1;
#pragma unroll
        for (int dr = 0; dr < 2; ++dr)
#pragma unroll
            for (int dc = 0; dc < 2; ++dc) {
                const float2 v = st[dr * 4 + (qc + dc)];
                s1 += v.x; q1 += v.y;
            }
        const float s0 = sh_half.x + phs, q0 = sh_half.y + phq;
        const float mu2 = f2.x * iN2; const float v2 = fmaxf(f2.y * iN2 - mu2 * mu2, 0.f);
        const float mu1 = s1  * iN1; const float v1 = fmaxf(q1  * iN1 - mu1 * mu1, 0.f);
        const float mu0 = s0  * iN0; const float v0 = fmaxf(q0  * iN0 - mu0 * mu0, 0.f);
        a2c = 0.5f * rsqrtf(v2 + EPS); b2c = -mu2 * a2c;
        a1c = 0.5f * rsqrtf(v1 + EPS); b1c = -mu1 * a1c;
        a0c = 0.5f * rsqrtf(v0 + EPS); b0c = -mu0 * a0c;
    }

    // Gate a float4: tanh via f16x2 (2 elems/MUFU op), args + blend in f32.
#define PMFM_GATE(res, vin, A2, B2, A1, B1, A0, B0)                            \
    {                                                                          \
        const float4 _v = (vin);                                               \
        const unsigned t2a = fast_tanh_h2(pack_h2(fmaf(_v.x, A2, B2), fmaf(_v.y, A2, B2))); \
        const unsigned t2b = fast_tanh_h2(pack_h2(fmaf(_v.z, A2, B2), fmaf(_v.w, A2, B2))); \
        const unsigned t1a = fast_tanh_h2(pack_h2(fmaf(_v.x, A1, B1), fmaf(_v.y, A1, B1))); \
        const unsigned t1b = fast_tanh_h2(pack_h2(fmaf(_v.z, A1, B1), fmaf(_v.w, A1, B1))); \
        const unsigned t0a = fast_tanh_h2(pack_h2(fmaf(_v.x, A0, B0), fmaf(_v.y, A0, B0))); \
        const unsigned t0b = fast_tanh_h2(pack_h2(fmaf(_v.z, A0, B0), fmaf(_v.w, A0, B0))); \
        const __half2 h2a = *(const __half2*)&t2a, h2b = *(const __half2*)&t2b; \
        const __half2 h1a = *(const __half2*)&t1a, h1b = *(const __half2*)&t1b; \
        const __half2 h0a = *(const __half2*)&t0a, h0b = *(const __half2*)&t0b; \
        (res).x = _v.x * fmaf(cf, __low2float(h2a),  fmaf(cm, __low2float(h1a),  fmaf(cg_, __low2float(h0a),  basew))); \
        (res).y = _v.y * fmaf(cf, __high2float(h2a), fmaf(cm, __high2float(h1a), fmaf(cg_, __high2float(h0a), basew))); \
        (res).z = _v.z * fmaf(cf, __low2float(h2b),  fmaf(cm, __low2float(h1b),  fmaf(cg_, __low2float(h0b),  basew))); \
        (res).w = _v.w * fmaf(cf, __high2float(h2b), fmaf(cm, __high2float(h1b), fmaf(cg_, __high2float(h0b), basew))); \
    }

    // ===== Stage 2: interleave B stats-reads (DRAM) with A gate+store =====
    float sb0 = 0.f, sb1 = 0.f, qb0 = 0.f, qb1 = 0.f;
#pragma unroll
    for (int c = 0; c < 16; ++c) {
        const float4 vb0 = pinB[(size_t)(2 * c + 0) * 128];
        const float4 vb1 = pinB[(size_t)(2 * c + 1) * 128];
        const float4 va0 = __ldcs(&pinA[(size_t)(2 * (15 - c) + 0) * 128]);
        const float4 va1 = __ldcs(&pinA[(size_t)(2 * (15 - c) + 1) * 128]);
        sb0 += (vb0.x + vb0.y) + (vb0.z + vb0.w);
        qb0 += vb0.x * vb0.x + vb0.y * vb0.y + vb0.z * vb0.z + vb0.w * vb0.w;
        sb1 += (vb1.x + vb1.y) + (vb1.z + vb1.w);
        qb1 += vb1.x * vb1.x + vb1.y * vb1.y + vb1.z * vb1.z + vb1.w * vb1.w;
        float4 r0, r1;
        PMFM_GATE(r0, va0, a2c, b2c, a1c, b1c, a0c, b0c);
        PMFM_GATE(r1, va1, a2c, b2c, a1c, b1c, a0c, b0c);
        __stcs(&poA[(size_t)(2 * (15 - c) + 0) * 128], r0);
        __stcs(&poA[(size_t)(2 * (15 - c) + 1) * 128], r1);
    }

    // ================= Stage 3: B stats exchange + apply =================
    float bs = sb0 + sb1, bq = qb0 + qb1;
#pragma unroll
    for (int o = 16; o > 0; o >>= 1) {
        bs += __shfl_xor_sync(0xffffffffu, bs, o);
        bq += __shfl_xor_sync(0xffffffffu, bq, o);
    }
    __syncthreads();               // everyone done reading st[] for A
    if (lane == 0) st[w] = make_float2(bs, bq);
    __syncthreads();
    if (t < 8) {
        float2 v = st[t];
        float hs = v.x, hq = v.y;
#pragma unroll
        for (int o = 4; o > 0; o >>= 1) {
            hs += __shfl_xor_sync(0x000000ffu, hs, o, 8);
            hq += __shfl_xor_sync(0x000000ffu, hq, o, 8);
        }
        if (t == 0) sh_half = make_float2(hs, hq);
    }
    cluster.sync();
    {
        float2 ph = make_float2(0.f, 0.f);
        if (lane == 0)
            ph = *(const float2*)cluster.map_shared_rank((void*)&sh_half, rank ^ 1u);
        phs = __shfl_sync(0xffffffffu, ph.x, 0);
        phq = __shfl_sync(0xffffffffu, ph.y, 0);
    }
    // Early arrive: done reading peer smem; matching wait at kernel end.
    asm volatile("barrier.cluster.arrive.aligned;" ::: "memory");
    {
        const float2 f2 = st[w];
        float s1 = 0.f, q1 = 0.f;
        const int qc = pcol & ~1;
#pragma unroll
        for (int dr = 0; dr < 2; ++dr)
#pragma unroll
            for (int dc = 0; dc < 2; ++dc) {
                const float2 v = st[dr * 4 + (qc + dc)];
                s1 += v.x; q1 += v.y;
            }
        const float s0 = sh_half.x + phs, q0 = sh_half.y + phq;
        const float mu2 = f2.x * iN2; const float v2 = fmaxf(f2.y * iN2 - mu2 * mu2, 0.f);
        const float mu1 = s1  * iN1; const float v1 = fmaxf(q1  * iN1 - mu1 * mu1, 0.f);
        const float mu0 = s0  * iN0; const float v0 = fmaxf(q0  * iN0 - mu0 * mu0, 0.f);
        a2c = 0.5f * rsqrtf(v2 + EPS); b2c = -mu2 * a2c;
        a1c = 0.5f * rsqrtf(v1 + EPS); b1c = -mu1 * a1c;
        a0c = 0.5f * rsqrtf(v0 + EPS); b0c = -mu0 * a0c;
    }
    // apply B: reverse-order L2-hot re-read, double-buffered
    float4 buf[2][2];
    buf[1][0] = __ldcs(&pinB[(size_t)(2 * 15 + 0) * 128]);
    buf[1][1] = __ldcs(&pinB[(size_t)(2 * 15 + 1) * 128]);
#pragma unroll
    for (int c = 15; c >= 0; --c) {
        const float4 cur0 = buf[c & 1][0];
        const float4 cur1 = buf[c & 1][1];
        if (c > 0) {
            buf[(c - 1) & 1][0] = __ldcs(&pinB[(size_t)(2 * (c - 1) + 0) * 128]);
            buf[(c - 1) & 1][1] = __ldcs(&pinB[(size_t)(2 * (c - 1) + 1) * 128]);
        }
        float4 r0, r1;
        PMFM_GATE(r0, cur0, a2c, b2c, a1c, b1c, a0c, b0c);
        PMFM_GATE(r1, cur1, a2c, b2c, a1c, b1c, a0c, b0c);
        __stcs(&poB[(size_t)(2 * c + 0) * 128], r0);
        __stcs(&poB[(size_t)(2 * c + 1) * 128], r1);
    }
#undef PMFM_GATE

    // No CTA exits while its peer might still read sh_half.
    asm volatile("barrier.cluster.wait.aligned;" ::: "memory");
}

extern "C" void kernel_launch(void* const* d_in, const int* in_sizes, int n_in,
                              void* d_out, int out_size) {
    const float* x;
    const float* lw;
    long nx;
    if (in_sizes[0] >= in_sizes[1]) {
        x = (const float*)d_in[0]; lw = (const float*)d_in[1]; nx = in_sizes[0];
    } else {
        x = (const float*)d_in[1]; lw = (const float*)d_in[0]; nx = in_sizes[1];
    }
    const int nplanes = (int)(nx / 65536);   // B*C = 512 planes of 256x256
    pmfm_fused<<<nplanes, 256>>>(x, lw, (float*)d_out);   // 2 planes / cluster
}

// round 12
// speedup vs baseline: 1.2116x; 1.0043x over previous
#include <cuda_runtime.h>
#include <cooperative_groups.h>
namespace cg = cooperative_groups;

#define THETA 0.5f
#define EPS   1e-5f

__device__ __forceinline__ float fast_tanh(float x) {
    float y;
    asm("tanh.approx.f32 %0, %1;" : "=f"(y) : "f"(x));
    return y;
}

// Cluster of 4 CTAs owns TWO adjacent planes A=2j, B=2j+1; CTA rank r owns
// the 128x128 level-1 QUADRANT r (qr=r>>1, qc=r&1) of both planes. Thus
// level-2 (64x64 patches) and level-1 (the quadrant itself) are CTA-local;
// only level-0 (plane) stats need a 3x float2 DSMEM pull per plane.
// 256 threads = 8 warps; warp pair (2p,2p+1) owns patch p (0..3) of the
// quadrant. Stage 1: stats(A) + exchange. Stage 2: B's stats loads (DRAM
// reads) interleaved with A's gate+store (L2 re-read + DRAM writes).
// Stage 3: exchange B, gate+store B (reverse, L2-hot, double-buffered).
__global__ __launch_bounds__(256, 8) __cluster_dims__(4, 1, 1)
void pmfm_fused(const float* __restrict__ x,
                const float* __restrict__ lw,
                float* __restrict__ out) {
    cg::cluster_group cluster = cg::this_cluster();
    const unsigned rank = cluster.block_rank();

    const int cid  = blockIdx.x >> 2;     // cluster id -> planes 2*cid, 2*cid+1
    const int t    = threadIdx.x;
    const int w    = t >> 5;              // warp 0..7
    const int lane = t & 31;
    const int pq   = w >> 1;              // patch 0..3 within quadrant

    const size_t planeA = (size_t)(2 * cid) * 65536;
    const int colf = (int)(rank & 1u) * 128 + (pq & 1) * 64 + (lane & 15) * 4;
    const int row  = (int)(rank >> 1) * 128 + (pq >> 1) * 64
                   + (lane >> 4) + ((w & 1) << 1);   // rows step 4 per k
    const size_t off = (size_t)row * 256 + colf;

    const float4* pinA = reinterpret_cast<const float4*>(x + planeA + off);
    const float4* pinB = reinterpret_cast<const float4*>(x + planeA + 65536 + off);
    float4*       poA  = reinterpret_cast<float4*>(out + planeA + off);
    float4*       poB  = reinterpret_cast<float4*>(out + planeA + 65536 + off);
    // per-thread: 16 float4 per plane, k-stride 4 rows = 256 float4

    __shared__ float2 stw[8];       // per-warp partials (half-patch each)
    __shared__ float2 sh_quad;      // this CTA's quadrant total (level-1!)

    // softmax(level_weights) — constant for both planes
    const float w0 = __ldg(lw + 0), w1 = __ldg(lw + 1), w2 = __ldg(lw + 2);
    const float mmx = fmaxf(w0, fmaxf(w1, w2));
    const float ew0 = __expf(w0 - mmx), ew1 = __expf(w1 - mmx), ew2 = __expf(w2 - mmx);
    const float cc = (1.f - THETA) * 0.5f / (ew0 + ew1 + ew2);
    const float cf = cc * ew0, cm = cc * ew1, cg_ = cc * ew2;
    const float basew = THETA + (1.f - THETA) * 0.5f;
    const float iN2 = 1.f / 4096.f, iN1 = 1.f / 16384.f, iN0 = 1.f / 65536.f;

#define PMFM_SUMSQ(v, S, Q)                                                  \
    S += ((v).x + (v).y) + ((v).z + (v).w);                                  \
    Q += (v).x * (v).x + (v).y * (v).y + (v).z * (v).z + (v).w * (v).w;

    // ================= Stage 1: stats over plane A =================
    float s = 0.f, q = 0.f, s2 = 0.f, q2 = 0.f;
#pragma unroll
    for (int c = 0; c < 4; ++c) {
        const float4 va = pinA[(size_t)(4 * c + 0) * 256];
        const float4 vb = pinA[(size_t)(4 * c + 1) * 256];
        const float4 vc = pinA[(size_t)(4 * c + 2) * 256];
        const float4 vd = pinA[(size_t)(4 * c + 3) * 256];
        PMFM_SUMSQ(va, s, q)  PMFM_SUMSQ(vb, s2, q2)
        PMFM_SUMSQ(vc, s, q)  PMFM_SUMSQ(vd, s2, q2)
    }
    s += s2; q += q2;
#pragma unroll
    for (int o = 16; o > 0; o >>= 1) {
        s += __shfl_xor_sync(0xffffffffu, s, o);
        q += __shfl_xor_sync(0xffffffffu, q, o);
    }
    if (lane == 0) stw[w] = make_float2(s, q);
    __syncthreads();
    if (t < 8) {
        float2 v = stw[t];
        float hs = v.x, hq = v.y;
#pragma unroll
        for (int o = 4; o > 0; o >>= 1) {
            hs += __shfl_xor_sync(0x000000ffu, hs, o, 8);
            hq += __shfl_xor_sync(0x000000ffu, hq, o, 8);
        }
        if (t == 0) sh_quad = make_float2(hs, hq);
    }
    cluster.sync();

    // level-0: pull 3 peers' quadrant totals (lanes 0..2, one peer each).
    // Safe vs peer overwrite in stage 3: that happens only after the peer's
    // ~15us stage 2, while this pull issues immediately after the sync.
    float s0, q0;
    {
        float2 pp = make_float2(0.f, 0.f);
        if (lane < 3) {
            const unsigned pr = (rank + 1u + (unsigned)lane) & 3u;
            pp = *(const float2*)cluster.map_shared_rank((void*)&sh_quad, pr);
        }
        s0 = sh_quad.x; q0 = sh_quad.y;
#pragma unroll
        for (int l = 0; l < 3; ++l) {
            s0 += __shfl_sync(0xffffffffu, pp.x, l);
            q0 += __shfl_sync(0xffffffffu, pp.y, l);
        }
    }
    // coefficients for A (level-1 = own quadrant; level-2 = warp-pair patch)
    float a2c, b2c, a1c, b1c, a0c, b0c;
    {
        const float2 ea = stw[2 * pq], eb = stw[2 * pq + 1];
        const float fs2 = ea.x + eb.x, fq2 = ea.y + eb.y;
        const float s1 = sh_quad.x, q1 = sh_quad.y;
        const float mu2 = fs2 * iN2; const float v2 = fmaxf(fq2 * iN2 - mu2 * mu2, 0.f);
        const float mu1 = s1  * iN1; const float v1 = fmaxf(q1  * iN1 - mu1 * mu1, 0.f);
        const float mu0 = s0  * iN0; const float v0 = fmaxf(q0  * iN0 - mu0 * mu0, 0.f);
        a2c = 0.5f * rsqrtf(v2 + EPS); b2c = -mu2 * a2c;
        a1c = 0.5f * rsqrtf(v1 + EPS); b1c = -mu1 * a1c;
        a0c = 0.5f * rsqrtf(v0 + EPS); b0c = -mu0 * a0c;
    }

#define PMFM_GATE(res, vin)                                                    \
    {                                                                          \
        const float4 _v = (vin);                                               \
        float* _r = (float*)&(res);                                            \
        const float* _x = (const float*)&_v;                                   \
        _Pragma("unroll")                                                      \
        for (int _k = 0; _k < 4; ++_k) {                                       \
            const float xx = _x[_k];                                           \
            const float tf = fast_tanh(fmaf(xx, a2c, b2c));                    \
            const float tm = fast_tanh(fmaf(xx, a1c, b1c));                    \
            const float tg = fast_tanh(fmaf(xx, a0c, b0c));                    \
            _r[_k] = xx * fmaf(cf, tf, fmaf(cm, tm, fmaf(cg_, tg, basew)));    \
        }                                                                      \
    }

    // ===== Stage 2: interleave B stats-reads (DRAM) with A gate+store =====
    float bs = 0.f, bq = 0.f, bs2 = 0.f, bq2 = 0.f;
#pragma unroll
    for (int c = 0; c < 8; ++c) {
        const float4 vb0 = pinB[(size_t)(2 * c + 0) * 256];
        const float4 vb1 = pinB[(size_t)(2 * c + 1) * 256];
        const float4 va0 = __ldcs(&pinA[(size_t)(2 * (7 - c) + 0) * 256]);
        const float4 va1 = __ldcs(&pinA[(size_t)(2 * (7 - c) + 1) * 256]);
        PMFM_SUMSQ(vb0, bs, bq)  PMFM_SUMSQ(vb1, bs2, bq2)
        float4 r0, r1;
        PMFM_GATE(r0, va0);
        PMFM_GATE(r1, va1);
        __stcs(&poA[(size_t)(2 * (7 - c) + 0) * 256], r0);
        __stcs(&poA[(size_t)(2 * (7 - c) + 1) * 256], r1);
    }

    // ================= Stage 3: B stats exchange + apply =================
    bs += bs2; bq += bq2;
#pragma unroll
    for (int o = 16; o > 0; o >>= 1) {
        bs += __shfl_xor_sync(0xffffffffu, bs, o);
        bq += __shfl_xor_sync(0xffffffffu, bq, o);
    }
    __syncthreads();               // all warps done reading stw A-values
    if (lane == 0) stw[w] = make_float2(bs, bq);
    __syncthreads();
    if (t < 8) {
        float2 v = stw[t];
        float hs = v.x, hq = v.y;
#pragma unroll
        for (int o = 4; o > 0; o >>= 1) {
            hs += __shfl_xor_sync(0x000000ffu, hs, o, 8);
            hq += __shfl_xor_sync(0x000000ffu, hq, o, 8);
        }
        if (t == 0) sh_quad = make_float2(hs, hq);
    }
    cluster.sync();
    {
        float2 pp = make_float2(0.f, 0.f);
        if (lane < 3) {
            const unsigned pr = (rank + 1u + (unsigned)lane) & 3u;
            pp = *(const float2*)cluster.map_shared_rank((void*)&sh_quad, pr);
        }
        s0 = sh_quad.x; q0 = sh_quad.y;
#pragma unroll
        for (int l = 0; l < 3; ++l) {
            s0 += __shfl_sync(0xffffffffu, pp.x, l);   // also forces pulls done
            q0 += __shfl_sync(0xffffffffu, pp.y, l);
        }
    }
    // Early arrive: done reading peer smem; matching wait at kernel end.
    asm volatile("barrier.cluster.arrive.aligned;" ::: "memory");
    {
        const float2 ea = stw[2 * pq], eb = stw[2 * pq + 1];
        const float fs2 = ea.x + eb.x, fq2 = ea.y + eb.y;
        const float s1 = sh_quad.x, q1 = sh_quad.y;
        const float mu2 = fs2 * iN2; const float v2 = fmaxf(fq2 * iN2 - mu2 * mu2, 0.f);
        const float mu1 = s1  * iN1; const float v1 = fmaxf(q1  * iN1 - mu1 * mu1, 0.f);
        const float mu0 = s0  * iN0; const float v0 = fmaxf(q0  * iN0 - mu0 * mu0, 0.f);
        a2c = 0.5f * rsqrtf(v2 + EPS); b2c = -mu2 * a2c;
        a1c = 0.5f * rsqrtf(v1 + EPS); b1c = -mu1 * a1c;
        a0c = 0.5f * rsqrtf(v0 + EPS); b0c = -mu0 * a0c;
    }
    // apply B: reverse-order L2-hot re-read, double-buffered
    float4 buf[2][2];
    buf[1][0] = __ldcs(&pinB[(size_t)(2 * 7 + 0) * 256]);
    buf[1][1] = __ldcs(&pinB[(size_t)(2 * 7 + 1) * 256]);
#pragma unroll
    for (int c = 7; c >= 0; --c) {
        const float4 cur0 = buf[c & 1][0];
        const float4 cur1 = buf[c & 1][1];
        if (c > 0) {
            buf[(c - 1) & 1][0] = __ldcs(&pinB[(size_t)(2 * (c - 1) + 0) * 256]);
            buf[(c - 1) & 1][1] = __ldcs(&pinB[(size_t)(2 * (c - 1) + 1) * 256]);
        }
        float4 r0, r1;
        PMFM_GATE(r0, cur0);
        PMFM_GATE(r1, cur1);
        __stcs(&poB[(size_t)(2 * c + 0) * 256], r0);
        __stcs(&poB[(size_t)(2 * c + 1) * 256], r1);
    }
#undef PMFM_GATE
#undef PMFM_SUMSQ

    // No CTA exits while its peers might still read sh_quad.
    asm volatile("barrier.cluster.wait.aligned;" ::: "memory");
}

extern "C" void kernel_launch(void* const* d_in, const int* in_sizes, int n_in,
                              void* d_out, int out_size) {
    const float* x;
    const float* lw;
    long nx;
    if (in_sizes[0] >= in_sizes[1]) {
        x = (const float*)d_in[0]; lw = (const float*)d_in[1]; nx = in_sizes[0];
    } else {
        x = (const float*)d_in[1]; lw = (const float*)d_in[0]; nx = in_sizes[1];
    }
    const int nplanes = (int)(nx / 65536);   // B*C = 512 planes of 256x256
    // 4 CTAs (quadrants) per plane pair -> 2 CTAs per plane
    pmfm_fused<<<nplanes * 2, 256>>>(x, lw, (float*)d_out);
}